// round 1
// baseline (speedup 1.0000x reference)
#include <cuda_runtime.h>
#include <math.h>

// Problem constants
#define Hc   256
#define Wc   256
#define KY   32     // retained ky modes
#define KX   64     // retained kx modes (0..31 and 224..255)
#define NIMG 256    // B*C = 8*32
#define NB   8
#define NCH  32

// ---------------- scratch (device globals; no allocation allowed) ----------
__device__ float2 g_T [NIMG * Hc * KY];   // stage A out: [img][h][ky]
__device__ float2 g_X [NIMG * KX * KY];   // stage B out: [img][kx][ky]
__device__ float2 g_Y [NIMG * KX * KY];   // stage C out
__device__ float2 g_T2[NIMG * Hc * KY];   // stage D out: [img][h][ky]
__device__ float2 g_Wt[2048 * 1024];      // transposed weights [kx*32+ky][i*32+o]
// twiddle tables
__device__ float2 g_FW[Wc * KY];          // [w][ky]  (cos, sin) of 2*pi*ky*w/256
__device__ float2 g_EH[Hc * KX];          // [h][kx]  (cos, sin) of 2*pi*kxv*h/256
__device__ float2 g_IW[KY * Wc];          // [ky][w]  c_ky/65536 * (cos, sin)

// ---------------- table init (fp64, exact mod-256 angle reduction) ---------
__global__ void k_tables() {
    int idx = blockIdx.x * blockDim.x + threadIdx.x;
    const double TWO_PI = 6.283185307179586476925286766559;
    if (idx < Wc * KY) {                       // FW
        int w = idx / KY, ky = idx % KY;
        double ang = TWO_PI * (double)((ky * w) & 255) / 256.0;
        g_FW[idx] = make_float2((float)cos(ang), (float)sin(ang));
        return;
    }
    int i2 = idx - Wc * KY;
    if (i2 < Hc * KX) {                        // EH
        int h = i2 / KX, kx = i2 % KX;
        int kxv = (kx < 32) ? kx : kx + 192;   // -32..-1 -> 224..255
        double ang = TWO_PI * (double)((kxv * h) & 255) / 256.0;
        g_EH[i2] = make_float2((float)cos(ang), (float)sin(ang));
        return;
    }
    int i3 = i2 - Hc * KX;
    if (i3 < KY * Wc) {                        // IW
        int ky = i3 / Wc, w = i3 % Wc;
        double c  = (ky == 0) ? 1.0 : 2.0;
        double sc = c / 65536.0;
        double ang = TWO_PI * (double)((ky * w) & 255) / 256.0;
        g_IW[i3] = make_float2((float)(sc * cos(ang)), (float)(sc * sin(ang)));
    }
}

// ---------------- weight transpose: [io][kxky] -> [kxky][io], pack (r,i) ---
__global__ void k_wtrans(const float* __restrict__ w1r, const float* __restrict__ w1i,
                         const float* __restrict__ w2r, const float* __restrict__ w2i) {
    __shared__ float2 tile[32][33];
    int z = blockIdx.z;                        // 0 -> w1, 1 -> w2
    const float* wr = z ? w2r : w1r;
    const float* wi = z ? w2i : w1i;
    int col = blockIdx.x * 32 + threadIdx.x;   // kxky within this array
#pragma unroll
    for (int j = 0; j < 4; j++) {
        int row = blockIdx.y * 32 + threadIdx.y + j * 8;   // io
        tile[threadIdx.y + j * 8][threadIdx.x] =
            make_float2(wr[row * 1024 + col], wi[row * 1024 + col]);
    }
    __syncthreads();
    int ocol = blockIdx.y * 32 + threadIdx.x;  // io
#pragma unroll
    for (int j = 0; j < 4; j++) {
        int orow = z * 1024 + blockIdx.x * 32 + threadIdx.y + j * 8;  // kxky global
        g_Wt[orow * 1024 + ocol] = tile[threadIdx.x][threadIdx.y + j * 8];
    }
}

// ---------------- stage A: T[img][h][ky] = sum_w x[h][w] * e^{-i th} --------
__global__ void __launch_bounds__(256) kA(const float* __restrict__ x) {
    __shared__ float xs[64][33];
    __shared__ __align__(16) float2 bs[32][34];
    int img = blockIdx.y;
    int h0  = blockIdx.x * 64;
    int t   = threadIdx.x;
    int ky0 = (t & 15) * 2;     // 2 ky per thread
    int hq  = (t >> 4) * 4;     // 4 h per thread
    const float* xp = x + (size_t)img * (Hc * Wc) + (size_t)h0 * Wc;

    float ar[4][2], ai[4][2];
#pragma unroll
    for (int j = 0; j < 4; j++) { ar[j][0]=ar[j][1]=ai[j][0]=ai[j][1]=0.f; }

    for (int w0 = 0; w0 < Wc; w0 += 32) {
#pragma unroll
        for (int r = 0; r < 8; r++) {          // 64x32 floats
            int e = t + r * 256; int hh = e >> 5, ww = e & 31;
            xs[hh][ww] = xp[hh * Wc + w0 + ww];
        }
#pragma unroll
        for (int r = 0; r < 4; r++) {          // 32x32 float2
            int e = t + r * 256; int ww = e >> 5, kk = e & 31;
            bs[ww][kk] = g_FW[(w0 + ww) * KY + kk];
        }
        __syncthreads();
#pragma unroll 8
        for (int w = 0; w < 32; w++) {
            float4 b2 = *(const float4*)&bs[w][ky0];   // c0,s0,c1,s1
#pragma unroll
            for (int j = 0; j < 4; j++) {
                float xv = xs[hq + j][w];
                ar[j][0] += xv * b2.x;  ai[j][0] -= xv * b2.y;
                ar[j][1] += xv * b2.z;  ai[j][1] -= xv * b2.w;
            }
        }
        __syncthreads();
    }
#pragma unroll
    for (int j = 0; j < 4; j++) {
        int h = h0 + hq + j;
        *(float4*)&g_T[((size_t)img * Hc + h) * KY + ky0] =
            make_float4(ar[j][0], ai[j][0], ar[j][1], ai[j][1]);
    }
}

// ---------------- stage B: X[img][kx][ky] = sum_h T[h][ky] * e^{-i th} -----
__global__ void __launch_bounds__(128) kB() {
    __shared__ __align__(16) float2 Tt[32][34];
    __shared__ float2 Et[32][33];
    int img = blockIdx.y;
    int kxb = blockIdx.x * 32;
    int t   = threadIdx.x;
    int ky0 = (t & 7) * 4;        // 4 ky
    int kxl = (t >> 3) * 2;       // 2 kx

    float xr[2][4], xi[2][4];
#pragma unroll
    for (int j = 0; j < 2; j++)
#pragma unroll
        for (int q = 0; q < 4; q++) { xr[j][q] = 0.f; xi[j][q] = 0.f; }

    for (int h0 = 0; h0 < Hc; h0 += 32) {
#pragma unroll
        for (int r = 0; r < 8; r++) {
            int e = t + r * 128; int hh = e >> 5, kk = e & 31;
            Tt[hh][kk] = g_T[((size_t)img * Hc + h0 + hh) * KY + kk];
            Et[hh][kk] = g_EH[(h0 + hh) * KX + kxb + kk];
        }
        __syncthreads();
#pragma unroll 4
        for (int h = 0; h < 32; h++) {
            float4 t01 = *(const float4*)&Tt[h][ky0];
            float4 t23 = *(const float4*)&Tt[h][ky0 + 2];
            float tr[4] = {t01.x, t01.z, t23.x, t23.z};
            float ti[4] = {t01.y, t01.w, t23.y, t23.w};
#pragma unroll
            for (int j = 0; j < 2; j++) {
                float2 e = Et[h][kxl + j];
#pragma unroll
                for (int q = 0; q < 4; q++) {
                    xr[j][q] += e.x * tr[q] + e.y * ti[q];
                    xi[j][q] += e.x * ti[q] - e.y * tr[q];
                }
            }
        }
        __syncthreads();
    }
#pragma unroll
    for (int j = 0; j < 2; j++) {
        size_t base = ((size_t)img * KX + kxb + kxl + j) * KY + ky0;
        *(float4*)&g_X[base]     = make_float4(xr[j][0], xi[j][0], xr[j][1], xi[j][1]);
        *(float4*)&g_X[base + 2] = make_float4(xr[j][2], xi[j][2], xr[j][3], xi[j][3]);
    }
}

// ---------------- stage C: Y[b,o] = sum_i X[b,i] * W[i,o]  per (kx,ky) -----
__global__ void __launch_bounds__(256) kC() {
    __shared__ float2 Ws[1024];
    __shared__ float2 Xs[256];
    int kk = blockIdx.x;          // kx*32+ky
    int t  = threadIdx.x;
#pragma unroll
    for (int r = 0; r < 4; r++) Ws[t + r * 256] = g_Wt[(size_t)kk * 1024 + t + r * 256];
    Xs[t] = g_X[(size_t)t * (KX * KY) + kk];
    __syncthreads();
    int b = t >> 5, o = t & 31;
    float yr = 0.f, yi = 0.f;
#pragma unroll
    for (int i = 0; i < 32; i++) {
        float2 xv = Xs[b * 32 + i];
        float2 wv = Ws[i * 32 + o];
        yr += xv.x * wv.x - xv.y * wv.y;
        yi += xv.x * wv.y + xv.y * wv.x;
    }
    g_Y[(size_t)t * (KX * KY) + kk] = make_float2(yr, yi);   // img = b*32+o = t
}

// ---------------- stage D: T2[img][h][ky] = sum_kx Y[kx][ky] * e^{+i th} ---
__global__ void __launch_bounds__(256) kD() {
    __shared__ float2 Et[64][33];
    __shared__ __align__(16) float2 Ys[32][34];
    int img = blockIdx.y;
    int h0  = blockIdx.x * 64;
    int t   = threadIdx.x;
    int ky0 = (t & 7) * 4;        // 4 ky
    int hl  = (t >> 3) * 2;       // 2 h

    float tr[2][4], ti[2][4];
#pragma unroll
    for (int j = 0; j < 2; j++)
#pragma unroll
        for (int q = 0; q < 4; q++) { tr[j][q] = 0.f; ti[j][q] = 0.f; }

    for (int kx0 = 0; kx0 < KX; kx0 += 32) {
#pragma unroll
        for (int r = 0; r < 8; r++) {
            int e = t + r * 256; int hh = e >> 5, kk = e & 31;
            Et[hh][kk] = g_EH[(h0 + hh) * KX + kx0 + kk];
        }
#pragma unroll
        for (int r = 0; r < 4; r++) {
            int e = t + r * 256; int rr = e >> 5, kk = e & 31;
            Ys[rr][kk] = g_Y[((size_t)img * KX + kx0 + rr) * KY + kk];
        }
        __syncthreads();
#pragma unroll 4
        for (int kx = 0; kx < 32; kx++) {
            float4 y01 = *(const float4*)&Ys[kx][ky0];
            float4 y23 = *(const float4*)&Ys[kx][ky0 + 2];
            float yr[4] = {y01.x, y01.z, y23.x, y23.z};
            float yi[4] = {y01.y, y01.w, y23.y, y23.w};
#pragma unroll
            for (int j = 0; j < 2; j++) {
                float2 e = Et[hl + j][kx];
#pragma unroll
                for (int q = 0; q < 4; q++) {
                    tr[j][q] += e.x * yr[q] - e.y * yi[q];
                    ti[j][q] += e.x * yi[q] + e.y * yr[q];
                }
            }
        }
        __syncthreads();
    }
#pragma unroll
    for (int j = 0; j < 2; j++) {
        size_t base = ((size_t)img * Hc + h0 + hl + j) * KY + ky0;
        *(float4*)&g_T2[base]     = make_float4(tr[j][0], ti[j][0], tr[j][1], ti[j][1]);
        *(float4*)&g_T2[base + 2] = make_float4(tr[j][2], ti[j][2], tr[j][3], ti[j][3]);
    }
}

// ---------------- stage E: out = sum_ky (cw*T2r - sw*T2i) + bias -----------
__global__ void __launch_bounds__(128) kE(const float* __restrict__ bias,
                                          float* __restrict__ out) {
    __shared__ __align__(16) float2 T2t[64][34];
    __shared__ __align__(16) float2 IWt[32][66];
    int img = blockIdx.z;
    int h0  = blockIdx.y * 64;
    int w0  = blockIdx.x * 64;
    int t   = threadIdx.x;
    int wq  = (t & 7) * 8;        // 8 w
    int hq  = (t >> 3) * 4;       // 4 h

#pragma unroll
    for (int r = 0; r < 16; r++) {
        int e = t + r * 128;
        { int hh = e >> 5, kk = e & 31;
          T2t[hh][kk] = g_T2[((size_t)img * Hc + h0 + hh) * KY + kk]; }
        { int kk = e >> 6, ww = e & 63;
          IWt[kk][ww] = g_IW[kk * Wc + w0 + ww]; }
    }
    __syncthreads();

    float acc[4][8];
#pragma unroll
    for (int j = 0; j < 4; j++)
#pragma unroll
        for (int q = 0; q < 8; q++) acc[j][q] = 0.f;

#pragma unroll 4
    for (int ky = 0; ky < 32; ky++) {
        float2 tv[4];
#pragma unroll
        for (int j = 0; j < 4; j++) tv[j] = T2t[hq + j][ky];
        float4 wA = *(const float4*)&IWt[ky][wq];
        float4 wB = *(const float4*)&IWt[ky][wq + 2];
        float4 wC = *(const float4*)&IWt[ky][wq + 4];
        float4 wD = *(const float4*)&IWt[ky][wq + 6];
        float cw[8] = {wA.x, wA.z, wB.x, wB.z, wC.x, wC.z, wD.x, wD.z};
        float sw[8] = {wA.y, wA.w, wB.y, wB.w, wC.y, wC.w, wD.y, wD.w};
#pragma unroll
        for (int j = 0; j < 4; j++)
#pragma unroll
            for (int q = 0; q < 8; q++)
                acc[j][q] += cw[q] * tv[j].x - sw[q] * tv[j].y;
    }

    float bv = bias[img & 31];
#pragma unroll
    for (int j = 0; j < 4; j++) {
        size_t base = ((size_t)img * Hc + h0 + hq + j) * Wc + w0 + wq;
        *(float4*)&out[base]     = make_float4(acc[j][0] + bv, acc[j][1] + bv,
                                               acc[j][2] + bv, acc[j][3] + bv);
        *(float4*)&out[base + 4] = make_float4(acc[j][4] + bv, acc[j][5] + bv,
                                               acc[j][6] + bv, acc[j][7] + bv);
    }
}

// ---------------- launch ----------------------------------------------------
extern "C" void kernel_launch(void* const* d_in, const int* in_sizes, int n_in,
                              void* d_out, int out_size) {
    const float* x    = (const float*)d_in[0];
    const float* w1r  = (const float*)d_in[1];
    const float* w1i  = (const float*)d_in[2];
    const float* w2r  = (const float*)d_in[3];
    const float* w2i  = (const float*)d_in[4];
    const float* bias = (const float*)d_in[5];
    float* out = (float*)d_out;

    k_tables<<<128, 256>>>();
    k_wtrans<<<dim3(32, 32, 2), dim3(32, 8)>>>(w1r, w1i, w2r, w2i);
    kA<<<dim3(4, 256), 256>>>(x);
    kB<<<dim3(2, 256), 128>>>();
    kC<<<2048, 256>>>();
    kD<<<dim3(4, 256), 256>>>();
    kE<<<dim3(4, 4, 256), 128>>>(bias, out);
}

// round 5
// speedup vs baseline: 1.0039x; 1.0039x over previous
#include <cuda_runtime.h>
#include <math.h>

// Problem constants
#define Hc   256
#define Wc   256
#define KY   32     // retained ky modes
#define KX   64     // retained kx modes (0..31 and 224..255)
#define NIMG 256    // B*C = 8*32
#define NB   8
#define NCH  32

// ---------------- scratch (device globals; no allocation allowed) ----------
__device__ float2 g_T [NIMG * Hc * KY];   // stage A out: [img][h][ky]
__device__ float2 g_X [NIMG * KX * KY];   // stage B out: [img][kx][ky]
__device__ float2 g_Y [NIMG * KX * KY];   // stage C out
__device__ float2 g_T2[NIMG * Hc * KY];   // stage D out: [img][h][ky]
__device__ float2 g_Wt[2048 * 1024];      // transposed weights [kx*32+ky][i*32+o]
// twiddle tables
__device__ float2 g_FW[Wc * KY];          // [w][ky]  (cos, sin) of 2*pi*ky*w/256
__device__ float2 g_EH[Hc * KX];          // [h][kx]  (cos, sin) of 2*pi*kxv*h/256
__device__ float2 g_IW[KY * Wc];          // [ky][w]  c_ky/65536 * (cos, sin)

// ---------------- table init (fp64, exact mod-256 angle reduction) ---------
__global__ void k_tables() {
    int idx = blockIdx.x * blockDim.x + threadIdx.x;
    const double TWO_PI = 6.283185307179586476925286766559;
    if (idx < Wc * KY) {                       // FW
        int w = idx / KY, ky = idx % KY;
        double ang = TWO_PI * (double)((ky * w) & 255) / 256.0;
        g_FW[idx] = make_float2((float)cos(ang), (float)sin(ang));
        return;
    }
    int i2 = idx - Wc * KY;
    if (i2 < Hc * KX) {                        // EH
        int h = i2 / KX, kx = i2 % KX;
        int kxv = (kx < 32) ? kx : kx + 192;   // -32..-1 -> 224..255
        double ang = TWO_PI * (double)((kxv * h) & 255) / 256.0;
        g_EH[i2] = make_float2((float)cos(ang), (float)sin(ang));
        return;
    }
    int i3 = i2 - Hc * KX;
    if (i3 < KY * Wc) {                        // IW
        int ky = i3 / Wc, w = i3 % Wc;
        double c  = (ky == 0) ? 1.0 : 2.0;
        double sc = c / 65536.0;
        double ang = TWO_PI * (double)((ky * w) & 255) / 256.0;
        g_IW[i3] = make_float2((float)(sc * cos(ang)), (float)(sc * sin(ang)));
    }
}

// ---------------- weight transpose: [io][kxky] -> [kxky][io], pack (r,i) ---
__global__ void k_wtrans(const float* __restrict__ w1r, const float* __restrict__ w1i,
                         const float* __restrict__ w2r, const float* __restrict__ w2i) {
    __shared__ float2 tile[32][33];
    int z = blockIdx.z;                        // 0 -> w1, 1 -> w2
    const float* wr = z ? w2r : w1r;
    const float* wi = z ? w2i : w1i;
    int col = blockIdx.x * 32 + threadIdx.x;   // kxky within this array
#pragma unroll
    for (int j = 0; j < 4; j++) {
        int row = blockIdx.y * 32 + threadIdx.y + j * 8;   // io
        tile[threadIdx.y + j * 8][threadIdx.x] =
            make_float2(wr[row * 1024 + col], wi[row * 1024 + col]);
    }
    __syncthreads();
    int ocol = blockIdx.y * 32 + threadIdx.x;  // io
#pragma unroll
    for (int j = 0; j < 4; j++) {
        int orow = z * 1024 + blockIdx.x * 32 + threadIdx.y + j * 8;  // kxky global
        g_Wt[orow * 1024 + ocol] = tile[threadIdx.x][threadIdx.y + j * 8];
    }
}

// ---------------- stage A: T[img][h][ky] = sum_w x[h][w] * e^{-i th} --------
__global__ void __launch_bounds__(256) kA(const float* __restrict__ x) {
    __shared__ float xs[64][33];
    __shared__ __align__(16) float2 bs[32][34];
    int img = blockIdx.y;
    int h0  = blockIdx.x * 64;
    int t   = threadIdx.x;
    int ky0 = (t & 15) * 2;     // 2 ky per thread
    int hq  = (t >> 4) * 4;     // 4 h per thread
    const float* xp = x + (size_t)img * (Hc * Wc) + (size_t)h0 * Wc;

    float ar[4][2], ai[4][2];
#pragma unroll
    for (int j = 0; j < 4; j++) { ar[j][0]=ar[j][1]=ai[j][0]=ai[j][1]=0.f; }

    for (int w0 = 0; w0 < Wc; w0 += 32) {
#pragma unroll
        for (int r = 0; r < 8; r++) {          // 64x32 floats
            int e = t + r * 256; int hh = e >> 5, ww = e & 31;
            xs[hh][ww] = xp[hh * Wc + w0 + ww];
        }
#pragma unroll
        for (int r = 0; r < 4; r++) {          // 32x32 float2
            int e = t + r * 256; int ww = e >> 5, kk = e & 31;
            bs[ww][kk] = g_FW[(w0 + ww) * KY + kk];
        }
        __syncthreads();
#pragma unroll 8
        for (int w = 0; w < 32; w++) {
            float4 b2 = *(const float4*)&bs[w][ky0];   // c0,s0,c1,s1
#pragma unroll
            for (int j = 0; j < 4; j++) {
                float xv = xs[hq + j][w];
                ar[j][0] += xv * b2.x;  ai[j][0] -= xv * b2.y;
                ar[j][1] += xv * b2.z;  ai[j][1] -= xv * b2.w;
            }
        }
        __syncthreads();
    }
#pragma unroll
    for (int j = 0; j < 4; j++) {
        int h = h0 + hq + j;
        *(float4*)&g_T[((size_t)img * Hc + h) * KY + ky0] =
            make_float4(ar[j][0], ai[j][0], ar[j][1], ai[j][1]);
    }
}

// ---------------- stage B: X[img][kx][ky] = sum_h T[h][ky] * e^{-i th} -----
__global__ void __launch_bounds__(128) kB() {
    __shared__ __align__(16) float2 Tt[32][34];
    __shared__ float2 Et[32][33];
    int img = blockIdx.y;
    int kxb = blockIdx.x * 32;
    int t   = threadIdx.x;
    int ky0 = (t & 7) * 4;        // 4 ky
    int kxl = (t >> 3) * 2;       // 2 kx

    float xr[2][4], xi[2][4];
#pragma unroll
    for (int j = 0; j < 2; j++)
#pragma unroll
        for (int q = 0; q < 4; q++) { xr[j][q] = 0.f; xi[j][q] = 0.f; }

    for (int h0 = 0; h0 < Hc; h0 += 32) {
#pragma unroll
        for (int r = 0; r < 8; r++) {
            int e = t + r * 128; int hh = e >> 5, kk = e & 31;
            Tt[hh][kk] = g_T[((size_t)img * Hc + h0 + hh) * KY + kk];
            Et[hh][kk] = g_EH[(h0 + hh) * KX + kxb + kk];
        }
        __syncthreads();
#pragma unroll 4
        for (int h = 0; h < 32; h++) {
            float4 t01 = *(const float4*)&Tt[h][ky0];
            float4 t23 = *(const float4*)&Tt[h][ky0 + 2];
            float tr[4] = {t01.x, t01.z, t23.x, t23.z};
            float ti[4] = {t01.y, t01.w, t23.y, t23.w};
#pragma unroll
            for (int j = 0; j < 2; j++) {
                float2 e = Et[h][kxl + j];
#pragma unroll
                for (int q = 0; q < 4; q++) {
                    xr[j][q] += e.x * tr[q] + e.y * ti[q];
                    xi[j][q] += e.x * ti[q] - e.y * tr[q];
                }
            }
        }
        __syncthreads();
    }
#pragma unroll
    for (int j = 0; j < 2; j++) {
        size_t base = ((size_t)img * KX + kxb + kxl + j) * KY + ky0;
        *(float4*)&g_X[base]     = make_float4(xr[j][0], xi[j][0], xr[j][1], xi[j][1]);
        *(float4*)&g_X[base + 2] = make_float4(xr[j][2], xi[j][2], xr[j][3], xi[j][3]);
    }
}

// ---------------- stage C: Y[b,o] = sum_i X[b,i] * W[i,o]  per (kx,ky) -----
__global__ void __launch_bounds__(256) kC() {
    __shared__ float2 Ws[1024];
    __shared__ float2 Xs[256];
    int kk = blockIdx.x;          // kx*32+ky
    int t  = threadIdx.x;
#pragma unroll
    for (int r = 0; r < 4; r++) Ws[t + r * 256] = g_Wt[(size_t)kk * 1024 + t + r * 256];
    Xs[t] = g_X[(size_t)t * (KX * KY) + kk];
    __syncthreads();
    int b = t >> 5, o = t & 31;
    float yr = 0.f, yi = 0.f;
#pragma unroll
    for (int i = 0; i < 32; i++) {
        float2 xv = Xs[b * 32 + i];
        float2 wv = Ws[i * 32 + o];
        yr += xv.x * wv.x - xv.y * wv.y;
        yi += xv.x * wv.y + xv.y * wv.x;
    }
    g_Y[(size_t)t * (KX * KY) + kk] = make_float2(yr, yi);   // img = b*32+o = t
}

// ---------------- stage D: T2[img][h][ky] = sum_kx Y[kx][ky] * e^{+i th} ---
__global__ void __launch_bounds__(256) kD() {
    __shared__ float2 Et[64][33];
    __shared__ __align__(16) float2 Ys[32][34];
    int img = blockIdx.y;
    int h0  = blockIdx.x * 64;
    int t   = threadIdx.x;
    int ky0 = (t & 7) * 4;        // 4 ky
    int hl  = (t >> 3) * 2;       // 2 h

    float tr[2][4], ti[2][4];
#pragma unroll
    for (int j = 0; j < 2; j++)
#pragma unroll
        for (int q = 0; q < 4; q++) { tr[j][q] = 0.f; ti[j][q] = 0.f; }

    for (int kx0 = 0; kx0 < KX; kx0 += 32) {
#pragma unroll
        for (int r = 0; r < 8; r++) {
            int e = t + r * 256; int hh = e >> 5, kk = e & 31;
            Et[hh][kk] = g_EH[(h0 + hh) * KX + kx0 + kk];
        }
#pragma unroll
        for (int r = 0; r < 4; r++) {
            int e = t + r * 256; int rr = e >> 5, kk = e & 31;
            Ys[rr][kk] = g_Y[((size_t)img * KX + kx0 + rr) * KY + kk];
        }
        __syncthreads();
#pragma unroll 4
        for (int kx = 0; kx < 32; kx++) {
            float4 y01 = *(const float4*)&Ys[kx][ky0];
            float4 y23 = *(const float4*)&Ys[kx][ky0 + 2];
            float yr[4] = {y01.x, y01.z, y23.x, y23.z};
            float yi[4] = {y01.y, y01.w, y23.y, y23.w};
#pragma unroll
            for (int j = 0; j < 2; j++) {
                float2 e = Et[hl + j][kx];
#pragma unroll
                for (int q = 0; q < 4; q++) {
                    tr[j][q] += e.x * yr[q] - e.y * yi[q];
                    ti[j][q] += e.x * yi[q] + e.y * yr[q];
                }
            }
        }
        __syncthreads();
    }
#pragma unroll
    for (int j = 0; j < 2; j++) {
        size_t base = ((size_t)img * Hc + h0 + hl + j) * KY + ky0;
        *(float4*)&g_T2[base]     = make_float4(tr[j][0], ti[j][0], tr[j][1], ti[j][1]);
        *(float4*)&g_T2[base + 2] = make_float4(tr[j][2], ti[j][2], tr[j][3], ti[j][3]);
    }
}

// ---------------- stage E: out = sum_ky (cw*T2r - sw*T2i) + bias -----------
__global__ void __launch_bounds__(128) kE(const float* __restrict__ bias,
                                          float* __restrict__ out) {
    __shared__ __align__(16) float2 T2t[64][34];
    __shared__ __align__(16) float2 IWt[32][66];
    int img = blockIdx.z;
    int h0  = blockIdx.y * 64;
    int w0  = blockIdx.x * 64;
    int t   = threadIdx.x;
    int wq  = (t & 7) * 8;        // 8 w
    int hq  = (t >> 3) * 4;       // 4 h

#pragma unroll
    for (int r = 0; r < 16; r++) {
        int e = t + r * 128;
        { int hh = e >> 5, kk = e & 31;
          T2t[hh][kk] = g_T2[((size_t)img * Hc + h0 + hh) * KY + kk]; }
        { int kk = e >> 6, ww = e & 63;
          IWt[kk][ww] = g_IW[kk * Wc + w0 + ww]; }
    }
    __syncthreads();

    float acc[4][8];
#pragma unroll
    for (int j = 0; j < 4; j++)
#pragma unroll
        for (int q = 0; q < 8; q++) acc[j][q] = 0.f;

#pragma unroll 4
    for (int ky = 0; ky < 32; ky++) {
        float2 tv[4];
#pragma unroll
        for (int j = 0; j < 4; j++) tv[j] = T2t[hq + j][ky];
        float4 wA = *(const float4*)&IWt[ky][wq];
        float4 wB = *(const float4*)&IWt[ky][wq + 2];
        float4 wC = *(const float4*)&IWt[ky][wq + 4];
        float4 wD = *(const float4*)&IWt[ky][wq + 6];
        float cw[8] = {wA.x, wA.z, wB.x, wB.z, wC.x, wC.z, wD.x, wD.z};
        float sw[8] = {wA.y, wA.w, wB.y, wB.w, wC.y, wC.w, wD.y, wD.w};
#pragma unroll
        for (int j = 0; j < 4; j++)
#pragma unroll
            for (int q = 0; q < 8; q++)
                acc[j][q] += cw[q] * tv[j].x - sw[q] * tv[j].y;
    }

    float bv = bias[img & 31];
#pragma unroll
    for (int j = 0; j < 4; j++) {
        size_t base = ((size_t)img * Hc + h0 + hq + j) * Wc + w0 + wq;
        *(float4*)&out[base]     = make_float4(acc[j][0] + bv, acc[j][1] + bv,
                                               acc[j][2] + bv, acc[j][3] + bv);
        *(float4*)&out[base + 4] = make_float4(acc[j][4] + bv, acc[j][5] + bv,
                                               acc[j][6] + bv, acc[j][7] + bv);
    }
}

// ---------------- launch ----------------------------------------------------
extern "C" void kernel_launch(void* const* d_in, const int* in_sizes, int n_in,
                              void* d_out, int out_size) {
    const float* x    = (const float*)d_in[0];
    const float* w1r  = (const float*)d_in[1];
    const float* w1i  = (const float*)d_in[2];
    const float* w2r  = (const float*)d_in[3];
    const float* w2i  = (const float*)d_in[4];
    const float* bias = (const float*)d_in[5];
    float* out = (float*)d_out;

    k_tables<<<128, 256>>>();
    k_wtrans<<<dim3(32, 32, 2), dim3(32, 8)>>>(w1r, w1i, w2r, w2i);
    kA<<<dim3(4, 256), 256>>>(x);
    kB<<<dim3(2, 256), 128>>>();
    kC<<<2048, 256>>>();
    kD<<<dim3(4, 256), 256>>>();
    kE<<<dim3(4, 4, 256), 128>>>(bias, out);
}

// round 6
// speedup vs baseline: 1.2889x; 1.2839x over previous
#include <cuda_runtime.h>
#include <math.h>

#define Hc 256
#define Wc 256
#define KY 32
#define NIMG 256

// ---------------- scratch ----------------
__device__ float2 g_T  [NIMG * Hc * KY];       // A out: [img][h][ky]
__device__ float2 g_XP [4 * NIMG * 64 * KY];   // B partials: [hs][img][kx][ky]
__device__ float2 g_Y  [NIMG * 64 * KY];       // C out: [img][kx][ky]
__device__ float2 g_T2 [NIMG * Hc * KY];       // D out: [img][h][ky]
__device__ float2 g_Wt [2048 * 1024];          // [kx*32+ky][i*32+o]
// tables
__device__ float2 g_csA[128 * 32];             // [w][ky]; w=0 -> (0.5,0)
__device__ float2 g_EH [Hc * 64];              // [h][kx]
__device__ float2 g_cs2[32 * 128];             // [ky][tw-1], tw=1..128: c*(cos,sin)

// ---------------- tables (fp64 exact) ----------------
__global__ void k_tables() {
    int idx = blockIdx.x * blockDim.x + threadIdx.x;
    const double TP = 6.283185307179586476925286766559;
    if (idx < 4096) {                          // csA
        int w = idx >> 5, ky = idx & 31;
        if (w == 0) { g_csA[idx] = make_float2(0.5f, 0.f); return; }
        double a = TP * (double)((ky * w) & 255) / 256.0;
        g_csA[idx] = make_float2((float)cos(a), (float)sin(a));
        return;
    }
    idx -= 4096;
    if (idx < 16384) {                         // EH
        int h = idx >> 6, kx = idx & 63;
        int kxv = (kx < 32) ? kx : kx + 192;
        double a = TP * (double)((kxv * h) & 255) / 256.0;
        g_EH[idx] = make_float2((float)cos(a), (float)sin(a));
        return;
    }
    idx -= 16384;
    if (idx < 4096) {                          // cs2 [ky][tw-1]
        int ky = idx >> 7, twm = idx & 127;
        int tw = twm + 1;
        double c = ((ky == 0) ? 1.0 : 2.0) / 65536.0;
        double a = TP * (double)((ky * tw) & 255) / 256.0;
        g_cs2[idx] = make_float2((float)(c * cos(a)), (float)(c * sin(a)));
    }
}

// ---------------- weight transpose ----------------
__global__ void k_wtrans(const float* __restrict__ w1r, const float* __restrict__ w1i,
                         const float* __restrict__ w2r, const float* __restrict__ w2i) {
    __shared__ float2 tile[32][33];
    int z = blockIdx.z;
    const float* wr = z ? w2r : w1r;
    const float* wi = z ? w2i : w1i;
    int col = blockIdx.x * 32 + threadIdx.x;
#pragma unroll
    for (int j = 0; j < 4; j++) {
        int row = blockIdx.y * 32 + threadIdx.y + j * 8;
        tile[threadIdx.y + j * 8][threadIdx.x] =
            make_float2(wr[row * 1024 + col], wi[row * 1024 + col]);
    }
    __syncthreads();
    int ocol = blockIdx.y * 32 + threadIdx.x;
#pragma unroll
    for (int j = 0; j < 4; j++) {
        int orow = z * 1024 + blockIdx.x * 32 + threadIdx.y + j * 8;
        g_Wt[(size_t)orow * 1024 + ocol] = tile[threadIdx.x][threadIdx.y + j * 8];
    }
}

// ---------------- stage A: u/v symmetric W-DFT ----------------
// T[h][ky] = sum_{w=0..127} u*C - i*v*S  (+ x[128]*(-1)^ky on Re)
__global__ void __launch_bounds__(128) kA(const float* __restrict__ x) {
    __shared__ float xa[64 * 33];
    __shared__ float xb[64 * 33];
    __shared__ __align__(16) float2 cst[32 * 34];
    int img = blockIdx.y, hb = blockIdx.x;
    int t = threadIdx.x;
    int ky0 = (t & 7) * 4;
    int hg  = (t >> 3) * 4;             // 0..60
    const float* xp = x + (size_t)img * 65536 + (size_t)hb * 64 * 256;

    float tr[4][4], ti[4][4];
#pragma unroll
    for (int j = 0; j < 4; j++)
#pragma unroll
        for (int q = 0; q < 4; q++) { tr[j][q] = 0.f; ti[j][q] = 0.f; }

    for (int c = 0; c < 4; c++) {
        int w0 = c * 32;
#pragma unroll
        for (int r = 0; r < 16; r++) {
            int e = t + r * 128; int l = e >> 5, ww = e & 31;
            xa[l * 33 + ww] = xp[l * 256 + w0 + ww];
            xb[l * 33 + ww] = xp[l * 256 + ((256 - w0 - ww) & 255)];
        }
#pragma unroll
        for (int r = 0; r < 8; r++) {
            int e = t + r * 128; int ww = e >> 5, kk = e & 31;
            cst[ww * 34 + kk] = g_csA[(w0 + ww) * 32 + kk];
        }
        __syncthreads();
#pragma unroll 4
        for (int ww = 0; ww < 32; ww++) {
            float u[4], v[4];
#pragma unroll
            for (int j = 0; j < 4; j++) {
                float a = xa[(hg + j) * 33 + ww];
                float b = xb[(hg + j) * 33 + ww];
                u[j] = a + b; v[j] = a - b;
            }
            float4 c01 = *(const float4*)&cst[ww * 34 + ky0];
            float4 c23 = *(const float4*)&cst[ww * 34 + ky0 + 2];
            float cc[4] = {c01.x, c01.z, c23.x, c23.z};
            float ss[4] = {c01.y, c01.w, c23.y, c23.w};
#pragma unroll
            for (int j = 0; j < 4; j++)
#pragma unroll
                for (int q = 0; q < 4; q++) {
                    tr[j][q] += u[j] * cc[q];
                    ti[j][q] -= v[j] * ss[q];
                }
        }
        __syncthreads();
    }
    // x[128] term: Re += x[128]*(-1)^ky  (ky0 multiple of 4 -> +,-,+,-)
#pragma unroll
    for (int j = 0; j < 4; j++) {
        float xv = xp[(hg + j) * 256 + 128];
        tr[j][0] += xv; tr[j][1] -= xv; tr[j][2] += xv; tr[j][3] -= xv;
    }
#pragma unroll
    for (int j = 0; j < 4; j++) {
        int h = hb * 64 + hg + j;
        size_t base = ((size_t)img * Hc + h) * KY + ky0;
        *(float4*)&g_T[base]     = make_float4(tr[j][0], ti[j][0], tr[j][1], ti[j][1]);
        *(float4*)&g_T[base + 2] = make_float4(tr[j][2], ti[j][2], tr[j][3], ti[j][3]);
    }
}

// ---------------- stage B: h-split H-DFT, 4kx x 4ky per thread -------------
__global__ void __launch_bounds__(128) kB() {
    __shared__ __align__(16) float2 Tt[32 * 34];
    __shared__ __align__(16) float2 Et[32 * 66];
    int img = blockIdx.y, hs = blockIdx.x;
    int t = threadIdx.x;
    int ky0 = (t & 7) * 4;
    int kxq = (t >> 3) * 4;             // 0..60

    float xr[4][4], xi[4][4];
#pragma unroll
    for (int j = 0; j < 4; j++)
#pragma unroll
        for (int q = 0; q < 4; q++) { xr[j][q] = 0.f; xi[j][q] = 0.f; }

    for (int c = 0; c < 2; c++) {
        int h0 = hs * 64 + c * 32;
#pragma unroll
        for (int r = 0; r < 8; r++) {
            int e = t + r * 128; int hh = e >> 5, kk = e & 31;
            Tt[hh * 34 + kk] = g_T[((size_t)img * Hc + h0 + hh) * KY + kk];
        }
#pragma unroll
        for (int r = 0; r < 16; r++) {
            int e = t + r * 128; int hh = e >> 6, kx = e & 63;
            Et[hh * 66 + kx] = g_EH[(h0 + hh) * 64 + kx];
        }
        __syncthreads();
#pragma unroll 4
        for (int hh = 0; hh < 32; hh++) {
            float4 t01 = *(const float4*)&Tt[hh * 34 + ky0];
            float4 t23 = *(const float4*)&Tt[hh * 34 + ky0 + 2];
            float trf[4] = {t01.x, t01.z, t23.x, t23.z};
            float tif[4] = {t01.y, t01.w, t23.y, t23.w};
            float4 eA = *(const float4*)&Et[hh * 66 + kxq];
            float4 eB = *(const float4*)&Et[hh * 66 + kxq + 2];
            float ec[4] = {eA.x, eA.z, eB.x, eB.z};
            float es[4] = {eA.y, eA.w, eB.y, eB.w};
#pragma unroll
            for (int j = 0; j < 4; j++)
#pragma unroll
                for (int q = 0; q < 4; q++) {
                    xr[j][q] += ec[j] * trf[q] + es[j] * tif[q];
                    xi[j][q] += ec[j] * tif[q] - es[j] * trf[q];
                }
        }
        __syncthreads();
    }
#pragma unroll
    for (int j = 0; j < 4; j++) {
        size_t base = (size_t)hs * 524288 + (size_t)img * 2048 + (kxq + j) * 32 + ky0;
        *(float4*)&g_XP[base]     = make_float4(xr[j][0], xi[j][0], xr[j][1], xi[j][1]);
        *(float4*)&g_XP[base + 2] = make_float4(xr[j][2], xi[j][2], xr[j][3], xi[j][3]);
    }
}

// ---------------- stage C: sum partials + channel mix per (kx,ky) ----------
__global__ void __launch_bounds__(256) kC() {
    __shared__ float2 Ws[1024];
    __shared__ float2 Xs[256];
    int kk = blockIdx.x;
    int t  = threadIdx.x;
#pragma unroll
    for (int r = 0; r < 4; r++) Ws[t + r * 256] = g_Wt[(size_t)kk * 1024 + t + r * 256];
    float2 s = g_XP[(size_t)t * 2048 + kk];
#pragma unroll
    for (int p = 1; p < 4; p++) {
        float2 v = g_XP[(size_t)p * 524288 + (size_t)t * 2048 + kk];
        s.x += v.x; s.y += v.y;
    }
    Xs[t] = s;
    __syncthreads();
    int b = t >> 5, o = t & 31;
    float yr = 0.f, yi = 0.f;
#pragma unroll
    for (int i = 0; i < 32; i++) {
        float2 xv = Xs[b * 32 + i];
        float2 wv = Ws[i * 32 + o];
        yr += xv.x * wv.x - xv.y * wv.y;
        yi += xv.x * wv.y + xv.y * wv.x;
    }
    g_Y[(size_t)t * 2048 + kk] = make_float2(yr, yi);
}

// ---------------- stage D: inverse H-DFT, 4h x 4ky per thread --------------
__global__ void __launch_bounds__(128) kD() {
    __shared__ __align__(16) float2 Ys[32 * 34];
    __shared__ float2 Eh[64 * 33];
    int img = blockIdx.y;
    int h0  = blockIdx.x * 64;
    int t = threadIdx.x;
    int ky0 = (t & 7) * 4;
    int hl  = (t >> 3) * 4;             // 0..60

    float tr[4][4], ti[4][4];
#pragma unroll
    for (int j = 0; j < 4; j++)
#pragma unroll
        for (int q = 0; q < 4; q++) { tr[j][q] = 0.f; ti[j][q] = 0.f; }

    for (int c = 0; c < 2; c++) {
        int kx0 = c * 32;
#pragma unroll
        for (int r = 0; r < 8; r++) {
            int e = t + r * 128; int kxl = e >> 5, kk = e & 31;
            Ys[kxl * 34 + kk] = g_Y[(size_t)img * 2048 + (kx0 + kxl) * 32 + kk];
        }
#pragma unroll
        for (int r = 0; r < 16; r++) {
            int e = t + r * 128; int hh = e >> 5, kxl = e & 31;
            Eh[hh * 33 + kxl] = g_EH[(h0 + hh) * 64 + kx0 + kxl];
        }
        __syncthreads();
#pragma unroll 4
        for (int kx = 0; kx < 32; kx++) {
            float4 y01 = *(const float4*)&Ys[kx * 34 + ky0];
            float4 y23 = *(const float4*)&Ys[kx * 34 + ky0 + 2];
            float yr[4] = {y01.x, y01.z, y23.x, y23.z};
            float yi[4] = {y01.y, y01.w, y23.y, y23.w};
#pragma unroll
            for (int j = 0; j < 4; j++) {
                float2 e = Eh[(hl + j) * 33 + kx];
#pragma unroll
                for (int q = 0; q < 4; q++) {
                    tr[j][q] += e.x * yr[q] - e.y * yi[q];
                    ti[j][q] += e.x * yi[q] + e.y * yr[q];
                }
            }
        }
        __syncthreads();
    }
#pragma unroll
    for (int j = 0; j < 4; j++) {
        size_t base = ((size_t)img * Hc + h0 + hl + j) * KY + ky0;
        *(float4*)&g_T2[base]     = make_float4(tr[j][0], ti[j][0], tr[j][1], ti[j][1]);
        *(float4*)&g_T2[base + 2] = make_float4(tr[j][2], ti[j][2], tr[j][3], ti[j][3]);
    }
}

// ---------------- stage E: symmetric inverse W-DFT + bias ------------------
// tw = wb*64 + slot + 1 (1..128); out[tw] = P-Q, out[256-tw] = P+Q
__global__ void __launch_bounds__(256) kE(const float* __restrict__ bias,
                                          float* __restrict__ out) {
    __shared__ __align__(16) float2 T2t[64 * 34];
    __shared__ __align__(16) float  csS[32 * 132];
    int img = blockIdx.z;
    int hb  = blockIdx.y;               // 0..3 (64 h each)
    int wb  = blockIdx.x;               // 0..1
    int t = threadIdx.x;
    int slot0 = (t & 15) * 4;           // 0..60
    int hq    = (t >> 4) * 4;           // 0..60

#pragma unroll
    for (int r = 0; r < 8; r++) {
        int e = t + r * 256; int hh = e >> 5, kk = e & 31;
        T2t[hh * 34 + kk] = g_T2[((size_t)img * Hc + hb * 64 + hh) * KY + kk];
    }
#pragma unroll
    for (int r = 0; r < 8; r++) {
        int e = t + r * 256; int ky = e >> 6, s = e & 63;
        float2 v = g_cs2[ky * 128 + wb * 64 + s];
        csS[ky * 132 + 2 * s]     = v.x;
        csS[ky * 132 + 2 * s + 1] = v.y;
    }
    __syncthreads();

    float P[4][4], Q[4][4];
#pragma unroll
    for (int j = 0; j < 4; j++)
#pragma unroll
        for (int q = 0; q < 4; q++) { P[j][q] = 0.f; Q[j][q] = 0.f; }

#pragma unroll 4
    for (int ky = 0; ky < 32; ky++) {
        float2 tv[4];
#pragma unroll
        for (int j = 0; j < 4; j++) tv[j] = T2t[(hq + j) * 34 + ky];
        float4 cA = *(const float4*)&csS[ky * 132 + 2 * slot0];
        float4 cB = *(const float4*)&csS[ky * 132 + 2 * slot0 + 4];
        float cc[4] = {cA.x, cA.z, cB.x, cB.z};
        float ss[4] = {cA.y, cA.w, cB.y, cB.w};
#pragma unroll
        for (int j = 0; j < 4; j++)
#pragma unroll
            for (int q = 0; q < 4; q++) {
                P[j][q] += cc[q] * tv[j].x;
                Q[j][q] += ss[q] * tv[j].y;
            }
    }

    float bv = bias[img & 31];
    int twb = wb * 64 + slot0 + 1;
#pragma unroll
    for (int j = 0; j < 4; j++) {
        size_t row = ((size_t)img * Hc + hb * 64 + hq + j) * Wc;
#pragma unroll
        for (int q = 0; q < 4; q++) {
            int tw = twb + q;
            out[row + tw]       = P[j][q] - Q[j][q] + bv;
            out[row + 256 - tw] = P[j][q] + Q[j][q] + bv;   // tw=128 rewrites same value
        }
    }
}

// ---------------- stage E0: w = 0 column ----------------
__global__ void kE0(const float* __restrict__ bias, float* __restrict__ out) {
    int img = blockIdx.x;
    int t = threadIdx.x, l = t & 31, wp = t >> 5;
    float coef = ((l == 0) ? 1.f : 2.f) * (1.f / 65536.f);
    float bv = bias[img & 31];
    for (int it = 0; it < 32; it++) {
        int h = wp + it * 8;
        float v = coef * g_T2[((size_t)img * Hc + h) * KY + l].x;
#pragma unroll
        for (int s = 16; s; s >>= 1) v += __shfl_xor_sync(0xffffffffu, v, s);
        if (l == 0) out[((size_t)img * Hc + h) * Wc] = v + bv;
    }
}

// ---------------- launch ----------------
extern "C" void kernel_launch(void* const* d_in, const int* in_sizes, int n_in,
                              void* d_out, int out_size) {
    const float* x    = (const float*)d_in[0];
    const float* w1r  = (const float*)d_in[1];
    const float* w1i  = (const float*)d_in[2];
    const float* w2r  = (const float*)d_in[3];
    const float* w2i  = (const float*)d_in[4];
    const float* bias = (const float*)d_in[5];
    float* out = (float*)d_out;

    k_tables<<<96, 256>>>();
    k_wtrans<<<dim3(32, 32, 2), dim3(32, 8)>>>(w1r, w1i, w2r, w2i);
    kA<<<dim3(4, 256), 128>>>(x);
    kB<<<dim3(4, 256), 128>>>();
    kC<<<2048, 256>>>();
    kD<<<dim3(4, 256), 128>>>();
    kE<<<dim3(2, 4, 256), 256>>>(bias, out);
    kE0<<<256, 256>>>(bias, out);
}

// round 7
// speedup vs baseline: 1.7854x; 1.3853x over previous
#include <cuda_runtime.h>
#include <math.h>

#define Hc 256
#define Wc 256
#define KY 32
#define NIMG 256
#define TPSZ 2097152   // NIMG*Hc*KY

// ---------------- scratch ----------------
__device__ float2 g_TP[2 * TPSZ];              // A partials [ws][img][h][ky]
__device__ float2 g_XP[4 * NIMG * 64 * KY];    // B partials [hs][img][kx][ky]
__device__ float2 g_Y [NIMG * 2048];           // C out [img][p][mm][ky]
__device__ float2 g_T2[NIMG * Hc * KY];        // D out [img][h][ky]
__device__ float2 g_Wt[2048 * 1024];           // [kx*32+ky][i*32+o]
// tables
__device__ float2 g_csA [128 * 32];            // [w][ky]; w=0 -> (0.5,0)
__device__ float2 g_E2  [128 * 32];            // [h'][mm] cos,sin of 2pi*m*h'/128
__device__ float2 g_w256[128];                 // cos,sin of 2pi*h/256
__device__ float2 g_cs2E[32 * 64];             // [ky][s] c*(cos,sin)(2pi*ky*(s+1)/256)

// ---------------- tables (fp64 exact) ----------------
__global__ void k_tables() {
    int idx = blockIdx.x * blockDim.x + threadIdx.x;
    const double TP = 6.283185307179586476925286766559;
    if (idx < 4096) {                          // csA
        int w = idx >> 5, ky = idx & 31;
        if (w == 0) { g_csA[idx] = make_float2(0.5f, 0.f); return; }
        double a = TP * (double)((ky * w) & 255) / 256.0;
        g_csA[idx] = make_float2((float)cos(a), (float)sin(a));
        return;
    }
    idx -= 4096;
    if (idx < 4096) {                          // E2
        int hp = idx >> 5, mm = idx & 31;
        int m = (mm < 16) ? mm : mm + 96;
        double a = TP * (double)((m * hp) & 127) / 128.0;
        g_E2[idx] = make_float2((float)cos(a), (float)sin(a));
        return;
    }
    idx -= 4096;
    if (idx < 128) {                           // w256
        double a = TP * (double)idx / 256.0;
        g_w256[idx] = make_float2((float)cos(a), (float)sin(a));
        return;
    }
    idx -= 128;
    if (idx < 2048) {                          // cs2E
        int ky = idx >> 6, s = idx & 63;
        int tw = s + 1;
        double c = ((ky == 0) ? 1.0 : 2.0) / 65536.0;
        double a = TP * (double)((ky * tw) & 255) / 256.0;
        g_cs2E[idx] = make_float2((float)(c * cos(a)), (float)(c * sin(a)));
    }
}

// ---------------- weight transpose ----------------
__global__ void k_wtrans(const float* __restrict__ w1r, const float* __restrict__ w1i,
                         const float* __restrict__ w2r, const float* __restrict__ w2i) {
    __shared__ float2 tile[32][33];
    int z = blockIdx.z;
    const float* wr = z ? w2r : w1r;
    const float* wi = z ? w2i : w1i;
    int col = blockIdx.x * 32 + threadIdx.x;
#pragma unroll
    for (int j = 0; j < 4; j++) {
        int row = blockIdx.y * 32 + threadIdx.y + j * 8;
        tile[threadIdx.y + j * 8][threadIdx.x] =
            make_float2(wr[row * 1024 + col], wi[row * 1024 + col]);
    }
    __syncthreads();
    int ocol = blockIdx.y * 32 + threadIdx.x;
#pragma unroll
    for (int j = 0; j < 4; j++) {
        int orow = z * 1024 + blockIdx.x * 32 + threadIdx.y + j * 8;
        g_Wt[(size_t)orow * 1024 + ocol] = tile[threadIdx.x][threadIdx.y + j * 8];
    }
}

// ---------------- stage A: u/v symmetric W-DFT, w-split x2 -----------------
__global__ void __launch_bounds__(128) kA(const float* __restrict__ x) {
    __shared__ float xa[64 * 33];
    __shared__ float xb[64 * 33];
    __shared__ __align__(16) float2 cst[32 * 34];
    int img = blockIdx.z, ws = blockIdx.y, hb = blockIdx.x;
    int t = threadIdx.x;
    int ky0 = (t & 7) * 4;
    int hg  = (t >> 3) * 4;
    const float* xp = x + (size_t)img * 65536 + (size_t)hb * 64 * 256;

    float tr[4][4], ti[4][4];
#pragma unroll
    for (int j = 0; j < 4; j++)
#pragma unroll
        for (int q = 0; q < 4; q++) { tr[j][q] = 0.f; ti[j][q] = 0.f; }

    for (int c = ws * 2; c < ws * 2 + 2; c++) {
        int w0 = c * 32;
#pragma unroll
        for (int r = 0; r < 16; r++) {
            int e = t + r * 128; int l = e >> 5, ww = e & 31;
            xa[l * 33 + ww] = xp[l * 256 + w0 + ww];
            xb[l * 33 + ww] = xp[l * 256 + ((256 - w0 - ww) & 255)];
        }
#pragma unroll
        for (int r = 0; r < 8; r++) {
            int e = t + r * 128; int ww = e >> 5, kk = e & 31;
            cst[ww * 34 + kk] = g_csA[(w0 + ww) * 32 + kk];
        }
        __syncthreads();
#pragma unroll 4
        for (int ww = 0; ww < 32; ww++) {
            float u[4], v[4];
#pragma unroll
            for (int j = 0; j < 4; j++) {
                float a = xa[(hg + j) * 33 + ww];
                float b = xb[(hg + j) * 33 + ww];
                u[j] = a + b; v[j] = a - b;
            }
            float4 c01 = *(const float4*)&cst[ww * 34 + ky0];
            float4 c23 = *(const float4*)&cst[ww * 34 + ky0 + 2];
            float cc[4] = {c01.x, c01.z, c23.x, c23.z};
            float ss[4] = {c01.y, c01.w, c23.y, c23.w};
#pragma unroll
            for (int j = 0; j < 4; j++)
#pragma unroll
                for (int q = 0; q < 4; q++) {
                    tr[j][q] += u[j] * cc[q];
                    ti[j][q] -= v[j] * ss[q];
                }
        }
        __syncthreads();
    }
    if (ws == 0) {   // x[128]*(-1)^ky term once
#pragma unroll
        for (int j = 0; j < 4; j++) {
            float xv = xp[(hg + j) * 256 + 128];
            tr[j][0] += xv; tr[j][1] -= xv; tr[j][2] += xv; tr[j][3] -= xv;
        }
    }
#pragma unroll
    for (int j = 0; j < 4; j++) {
        int h = hb * 64 + hg + j;
        size_t base = (size_t)ws * TPSZ + ((size_t)img * Hc + h) * KY + ky0;
        *(float4*)&g_TP[base]     = make_float4(tr[j][0], ti[j][0], tr[j][1], ti[j][1]);
        *(float4*)&g_TP[base + 2] = make_float4(tr[j][2], ti[j][2], tr[j][3], ti[j][3]);
    }
}

// ------- stage B: radix-2 H-DFT. Block = 32 h' chunk; outputs kx=2mm,2mm+1 --
__global__ void __launch_bounds__(128) kB() {
    __shared__ __align__(16) float2 Ut[32 * 34];
    __shared__ __align__(16) float2 Vt[32 * 34];
    __shared__ float2 Et[32 * 34];
    int img = blockIdx.y, hs = blockIdx.x;
    int h0 = hs * 32;
    int t = threadIdx.x;
    int ky0 = (t & 7) * 4;
    int mm0 = (t >> 3) * 2;

    float er[2][2][4], ei[2][2][4];   // [parity][m][ky]
#pragma unroll
    for (int p = 0; p < 2; p++)
#pragma unroll
        for (int m = 0; m < 2; m++)
#pragma unroll
            for (int q = 0; q < 4; q++) { er[p][m][q] = 0.f; ei[p][m][q] = 0.f; }

#pragma unroll
    for (int r = 0; r < 8; r++) {
        int e = t + r * 128; int hh = e >> 5, kk = e & 31;
        size_t ia = ((size_t)img * Hc + h0 + hh) * KY + kk;
        size_t ib = ((size_t)img * Hc + h0 + hh + 128) * KY + kk;
        float2 a  = g_TP[ia], a2 = g_TP[TPSZ + ia];
        float2 b  = g_TP[ib], b2 = g_TP[TPSZ + ib];
        a.x += a2.x; a.y += a2.y; b.x += b2.x; b.y += b2.y;
        Ut[hh * 34 + kk] = make_float2(a.x + b.x, a.y + b.y);
        float dx = a.x - b.x, dy = a.y - b.y;
        float2 w = g_w256[h0 + hh];   // e^{-i th}: (c,-s)
        Vt[hh * 34 + kk] = make_float2(dx * w.x + dy * w.y, dy * w.x - dx * w.y);
        Et[hh * 34 + kk] = g_E2[(h0 + hh) * 32 + kk];
    }
    __syncthreads();
#pragma unroll 4
    for (int hh = 0; hh < 32; hh++) {
        float4 u01 = *(const float4*)&Ut[hh * 34 + ky0];
        float4 u23 = *(const float4*)&Ut[hh * 34 + ky0 + 2];
        float4 v01 = *(const float4*)&Vt[hh * 34 + ky0];
        float4 v23 = *(const float4*)&Vt[hh * 34 + ky0 + 2];
        float ur[4] = {u01.x, u01.z, u23.x, u23.z};
        float ui[4] = {u01.y, u01.w, u23.y, u23.w};
        float vr[4] = {v01.x, v01.z, v23.x, v23.z};
        float vi[4] = {v01.y, v01.w, v23.y, v23.w};
#pragma unroll
        for (int m = 0; m < 2; m++) {
            float2 e = Et[hh * 34 + mm0 + m];
#pragma unroll
            for (int q = 0; q < 4; q++) {
                er[0][m][q] += e.x * ur[q] + e.y * ui[q];
                ei[0][m][q] += e.x * ui[q] - e.y * ur[q];
                er[1][m][q] += e.x * vr[q] + e.y * vi[q];
                ei[1][m][q] += e.x * vi[q] - e.y * vr[q];
            }
        }
    }
#pragma unroll
    for (int m = 0; m < 2; m++)
#pragma unroll
        for (int p = 0; p < 2; p++) {
            int kx = 2 * (mm0 + m) + p;
            size_t base = (size_t)hs * 524288 + (size_t)img * 2048 + kx * 32 + ky0;
            *(float4*)&g_XP[base] =
                make_float4(er[p][m][0], ei[p][m][0], er[p][m][1], ei[p][m][1]);
            *(float4*)&g_XP[base + 2] =
                make_float4(er[p][m][2], ei[p][m][2], er[p][m][3], ei[p][m][3]);
        }
}

// ---------------- stage C: sum partials + channel mix ----------------------
__global__ void __launch_bounds__(256) kC() {
    __shared__ float2 Ws[1024];
    __shared__ float2 Xs[256];
    int kk = blockIdx.x;
    int t  = threadIdx.x;
#pragma unroll
    for (int r = 0; r < 4; r++) Ws[t + r * 256] = g_Wt[(size_t)kk * 1024 + t + r * 256];
    float2 s = g_XP[(size_t)t * 2048 + kk];
#pragma unroll
    for (int p = 1; p < 4; p++) {
        float2 v = g_XP[(size_t)p * 524288 + (size_t)t * 2048 + kk];
        s.x += v.x; s.y += v.y;
    }
    Xs[t] = s;
    __syncthreads();
    int b = t >> 5, o = t & 31;
    float yr = 0.f, yi = 0.f;
#pragma unroll
    for (int i = 0; i < 32; i++) {
        float2 xv = Xs[b * 32 + i];
        float2 wv = Ws[i * 32 + o];
        yr += xv.x * wv.x - xv.y * wv.y;
        yi += xv.x * wv.y + xv.y * wv.x;
    }
    // write parity-split: [img][p][mm][ky]
    int p = (kk >> 5) & 1, mm = kk >> 6, ky = kk & 31;
    g_Y[(size_t)t * 2048 + p * 1024 + mm * 32 + ky] = make_float2(yr, yi);
}

// ------- stage D: radix-2 inverse H-DFT. Block = 32 h' -> 64 output rows ---
__global__ void __launch_bounds__(128) kD() {
    __shared__ __align__(16) float2 Ye[32 * 34];
    __shared__ __align__(16) float2 Yo[32 * 34];
    __shared__ float2 Eh[32 * 34];
    int img = blockIdx.y, hs = blockIdx.x;
    int h0 = hs * 32;
    int t = threadIdx.x;
    int ky0 = (t & 7) * 4;
    int hl  = (t >> 3) * 2;

#pragma unroll
    for (int r = 0; r < 8; r++) {
        int e = t + r * 128; int a = e >> 5, b = e & 31;
        Ye[a * 34 + b] = g_Y[(size_t)img * 2048 + a * 32 + b];
        Yo[a * 34 + b] = g_Y[(size_t)img * 2048 + 1024 + a * 32 + b];
        Eh[a * 34 + b] = g_E2[(h0 + a) * 32 + b];
    }
    __syncthreads();

    float aer[2][4], aei[2][4], aor[2][4], aoi[2][4];
#pragma unroll
    for (int j = 0; j < 2; j++)
#pragma unroll
        for (int q = 0; q < 4; q++) { aer[j][q]=0.f; aei[j][q]=0.f; aor[j][q]=0.f; aoi[j][q]=0.f; }

#pragma unroll 4
    for (int mm = 0; mm < 32; mm++) {
        float4 e01 = *(const float4*)&Ye[mm * 34 + ky0];
        float4 e23 = *(const float4*)&Ye[mm * 34 + ky0 + 2];
        float4 o01 = *(const float4*)&Yo[mm * 34 + ky0];
        float4 o23 = *(const float4*)&Yo[mm * 34 + ky0 + 2];
        float yer[4] = {e01.x, e01.z, e23.x, e23.z};
        float yei[4] = {e01.y, e01.w, e23.y, e23.w};
        float yor[4] = {o01.x, o01.z, o23.x, o23.z};
        float yoi[4] = {o01.y, o01.w, o23.y, o23.w};
#pragma unroll
        for (int j = 0; j < 2; j++) {
            float2 e = Eh[(hl + j) * 34 + mm];   // e^{+i}: (c, s)
#pragma unroll
            for (int q = 0; q < 4; q++) {
                aer[j][q] += e.x * yer[q] - e.y * yei[q];
                aei[j][q] += e.x * yei[q] + e.y * yer[q];
                aor[j][q] += e.x * yor[q] - e.y * yoi[q];
                aoi[j][q] += e.x * yoi[q] + e.y * yor[q];
            }
        }
    }
#pragma unroll
    for (int j = 0; j < 2; j++) {
        int hp = h0 + hl + j;
        float2 w = g_w256[hp];   // e^{+i 2pi hp/256}
        float pr[4], pi[4], mr[4], mi[4];
#pragma unroll
        for (int q = 0; q < 4; q++) {
            float sr = aor[j][q] * w.x - aoi[j][q] * w.y;
            float si = aoi[j][q] * w.x + aor[j][q] * w.y;
            pr[q] = aer[j][q] + sr; pi[q] = aei[j][q] + si;
            mr[q] = aer[j][q] - sr; mi[q] = aei[j][q] - si;
        }
        size_t b1 = ((size_t)img * Hc + hp) * KY + ky0;
        size_t b2 = ((size_t)img * Hc + hp + 128) * KY + ky0;
        *(float4*)&g_T2[b1]     = make_float4(pr[0], pi[0], pr[1], pi[1]);
        *(float4*)&g_T2[b1 + 2] = make_float4(pr[2], pi[2], pr[3], pi[3]);
        *(float4*)&g_T2[b2]     = make_float4(mr[0], mi[0], mr[1], mi[1]);
        *(float4*)&g_T2[b2 + 2] = make_float4(mr[2], mi[2], mr[3], mi[3]);
    }
}

// ------- stage E: ky-parity-folded inverse W-DFT (4 cols per cell) ---------
__global__ void __launch_bounds__(256) kE(const float* __restrict__ bias,
                                          float* __restrict__ out) {
    __shared__ __align__(16) float2 T2s[32 * 66];   // [ky][h]
    __shared__ __align__(16) float2 csE[32 * 34];   // [ky][s_local]
    int img = blockIdx.z;
    int hb  = blockIdx.y;            // 0..3 (64 h)
    int wb  = blockIdx.x;            // 0..1 (32 s)
    int t = threadIdx.x;
    int sl = (t & 15) * 2;           // 2 s per thread
    int hq = (t >> 4) * 4;           // 4 h per thread

#pragma unroll
    for (int r = 0; r < 8; r++) {
        int e = t + r * 256; int ky = e & 31, h = e >> 5;
        T2s[ky * 66 + h] = g_T2[((size_t)img * Hc + hb * 64 + h) * KY + ky];
    }
#pragma unroll
    for (int r = 0; r < 4; r++) {
        int e = t + r * 256; int ky = e >> 5, s = e & 31;
        csE[ky * 34 + s] = g_cs2E[ky * 64 + wb * 32 + s];
    }
    __syncthreads();

    float Pe[4][2], Po[4][2], Qe[4][2], Qo[4][2];
#pragma unroll
    for (int j = 0; j < 4; j++)
#pragma unroll
        for (int q = 0; q < 2; q++) { Pe[j][q]=0.f; Po[j][q]=0.f; Qe[j][q]=0.f; Qo[j][q]=0.f; }

#pragma unroll
    for (int ky = 0; ky < 32; ky++) {
        float4 t01 = *(const float4*)&T2s[ky * 66 + hq];
        float4 t23 = *(const float4*)&T2s[ky * 66 + hq + 2];
        float trv[4] = {t01.x, t01.z, t23.x, t23.z};
        float tiv[4] = {t01.y, t01.w, t23.y, t23.w};
        float4 cs = *(const float4*)&csE[ky * 34 + sl];   // c0,s0,c1,s1
        float cc[2] = {cs.x, cs.z};
        float ss[2] = {cs.y, cs.w};
        if ((ky & 1) == 0) {
#pragma unroll
            for (int j = 0; j < 4; j++)
#pragma unroll
                for (int q = 0; q < 2; q++) {
                    Pe[j][q] += cc[q] * trv[j];
                    Qe[j][q] += ss[q] * tiv[j];
                }
        } else {
#pragma unroll
            for (int j = 0; j < 4; j++)
#pragma unroll
                for (int q = 0; q < 2; q++) {
                    Po[j][q] += cc[q] * trv[j];
                    Qo[j][q] += ss[q] * tiv[j];
                }
        }
    }

    float bv = bias[img & 31];
#pragma unroll
    for (int j = 0; j < 4; j++) {
        size_t row = ((size_t)img * Hc + hb * 64 + hq + j) * Wc;
#pragma unroll
        for (int q = 0; q < 2; q++) {
            int tw = wb * 32 + sl + q + 1;      // 1..64
            float Pp = Pe[j][q] + Po[j][q], Pm = Pe[j][q] - Po[j][q];
            float Qp = Qe[j][q] + Qo[j][q], Qm = Qe[j][q] - Qo[j][q];
            out[row + tw]        = Pp - Qp + bv;
            out[row + 256 - tw]  = Pp + Qp + bv;
            out[row + 128 - tw]  = Pm + Qm + bv;
            out[row + 128 + tw]  = Pm - Qm + bv;
        }
    }
}

// ---------------- stage E0: w = 0 and w = 128 columns ----------------------
__global__ void kE0(const float* __restrict__ bias, float* __restrict__ out) {
    int img = blockIdx.x;
    int t = threadIdx.x, l = t & 31, wp = t >> 5;
    float coef = ((l == 0) ? 1.f : 2.f) * (1.f / 65536.f);
    float sgn  = (l & 1) ? -1.f : 1.f;
    float bv = bias[img & 31];
    for (int it = 0; it < 32; it++) {
        int h = wp + it * 8;
        float a = coef * g_T2[((size_t)img * Hc + h) * KY + l].x;
        float b = sgn * a;
#pragma unroll
        for (int s = 16; s; s >>= 1) {
            a += __shfl_xor_sync(0xffffffffu, a, s);
            b += __shfl_xor_sync(0xffffffffu, b, s);
        }
        if (l == 0) {
            size_t row = ((size_t)img * Hc + h) * Wc;
            out[row]       = a + bv;
            out[row + 128] = b + bv;
        }
    }
}

// ---------------- launch ----------------
extern "C" void kernel_launch(void* const* d_in, const int* in_sizes, int n_in,
                              void* d_out, int out_size) {
    const float* x    = (const float*)d_in[0];
    const float* w1r  = (const float*)d_in[1];
    const float* w1i  = (const float*)d_in[2];
    const float* w2r  = (const float*)d_in[3];
    const float* w2i  = (const float*)d_in[4];
    const float* bias = (const float*)d_in[5];
    float* out = (float*)d_out;

    k_tables<<<48, 256>>>();
    k_wtrans<<<dim3(32, 32, 2), dim3(32, 8)>>>(w1r, w1i, w2r, w2i);
    kA<<<dim3(4, 2, 256), 128>>>(x);
    kB<<<dim3(4, 256), 128>>>();
    kC<<<2048, 256>>>();
    kD<<<dim3(4, 256), 128>>>();
    kE<<<dim3(2, 4, 256), 256>>>(bias, out);
    kE0<<<256, 256>>>(bias, out);
}

// round 8
// speedup vs baseline: 1.9477x; 1.0909x over previous
#include <cuda_runtime.h>
#include <math.h>

#define Hc 256
#define Wc 256
#define KY 32
#define NIMG 256

// ---------------- scratch ----------------
__device__ float2 g_T [NIMG * Hc * KY];        // A out [img][h][ky]
__device__ float2 g_XP[4 * NIMG * 64 * KY];    // B partials [hs][img][kx][ky]
__device__ float2 g_Y [NIMG * 2048];           // C out [img][p][mm][ky]
__device__ float2 g_T2[NIMG * Hc * KY];        // D out [img][h][ky]
__device__ float2 g_Wt[2048 * 1024];           // [kx*32+ky][i*32+o]
// tables
__device__ float2 g_csA [128 * 32];            // [w][ky] cos,sin 2pi*ky*w/256
__device__ float2 g_E2  [128 * 32];            // [h'][mm] cos,sin 2pi*m*h'/128
__device__ float2 g_w256[128];                 // cos,sin 2pi*h/256
__device__ float2 g_cs2E[32 * 64];             // [ky][s] c*(cos,sin)(2pi*ky*(s+1)/256)

// ---------------- tables (fp64 exact) ----------------
__global__ void k_tables() {
    int idx = blockIdx.x * blockDim.x + threadIdx.x;
    const double TP = 6.283185307179586476925286766559;
    if (idx < 4096) {                          // csA
        int w = idx >> 5, ky = idx & 31;
        double a = TP * (double)((ky * w) & 255) / 256.0;
        g_csA[idx] = make_float2((float)cos(a), (float)sin(a));
        return;
    }
    idx -= 4096;
    if (idx < 4096) {                          // E2
        int hp = idx >> 5, mm = idx & 31;
        int m = (mm < 16) ? mm : mm + 96;
        double a = TP * (double)((m * hp) & 127) / 128.0;
        g_E2[idx] = make_float2((float)cos(a), (float)sin(a));
        return;
    }
    idx -= 4096;
    if (idx < 128) {                           // w256
        double a = TP * (double)idx / 256.0;
        g_w256[idx] = make_float2((float)cos(a), (float)sin(a));
        return;
    }
    idx -= 128;
    if (idx < 2048) {                          // cs2E
        int ky = idx >> 6, s = idx & 63;
        int tw = s + 1;
        double c = ((ky == 0) ? 1.0 : 2.0) / 65536.0;
        double a = TP * (double)((ky * tw) & 255) / 256.0;
        g_cs2E[idx] = make_float2((float)(c * cos(a)), (float)(c * sin(a)));
    }
}

// ---------------- weight transpose ----------------
__global__ void k_wtrans(const float* __restrict__ w1r, const float* __restrict__ w1i,
                         const float* __restrict__ w2r, const float* __restrict__ w2i) {
    __shared__ float2 tile[32][33];
    int z = blockIdx.z;
    const float* wr = z ? w2r : w1r;
    const float* wi = z ? w2i : w1i;
    int col = blockIdx.x * 32 + threadIdx.x;
#pragma unroll
    for (int j = 0; j < 4; j++) {
        int row = blockIdx.y * 32 + threadIdx.y + j * 8;
        tile[threadIdx.y + j * 8][threadIdx.x] =
            make_float2(wr[row * 1024 + col], wi[row * 1024 + col]);
    }
    __syncthreads();
    int ocol = blockIdx.y * 32 + threadIdx.x;
#pragma unroll
    for (int j = 0; j < 4; j++) {
        int orow = z * 1024 + blockIdx.x * 32 + threadIdx.y + j * 8;
        g_Wt[(size_t)orow * 1024 + ocol] = tile[threadIdx.x][threadIdx.y + j * 8];
    }
}

// ------- stage A: doubly-folded W-DFT (u/v + ky-parity), 268M FMA ----------
// Re(ky) = x0 + sum_{w=1..63} (ky even? ue:uo)(w) cos(2pi ky w/256)
//          + u64*cos(pi ky/2) + x128*(-1)^ky
// Im(ky) = -sum_{w=1..63} (ky even? ve:vo)(w) sin(...) - v64*sin(pi ky/2)
__global__ void __launch_bounds__(128) kA(const float* __restrict__ x) {
    __shared__ __align__(16) float sue[16 * 76];
    __shared__ __align__(16) float suo[16 * 76];
    __shared__ __align__(16) float sve[16 * 76];
    __shared__ __align__(16) float svo[16 * 76];
    __shared__ __align__(16) float2 scs[16 * 34];
    int img = blockIdx.y, hb = blockIdx.x;      // 64 h per block
    int t = threadIdx.x;
    int hg  = t & 15;                           // h_local = hg*4 + j
    int kyg = t >> 4;                           // ky0 = kyg*4
    int ky0 = kyg * 4;
    const float* xp = x + (size_t)img * 65536 + (size_t)hb * 64 * 256;

    float tr[4][4], ti[4][4];
#pragma unroll
    for (int j = 0; j < 4; j++)
#pragma unroll
        for (int q = 0; q < 4; q++) { tr[j][q] = 0.f; ti[j][q] = 0.f; }

    for (int wc = 0; wc < 4; wc++) {
        // fill: butterflies precomputed once per (h, w-pair)
#pragma unroll
        for (int r = 0; r < 8; r++) {
            int e = t + r * 128;                // 0..1023
            int wl = e & 15, hh = e >> 4;       // coalesced over wl
            int w = wc * 16 + wl + 1;           // 1..64
            float a1 = xp[hh * 256 + w];
            float b1 = xp[hh * 256 + 256 - w];
            float a2 = xp[hh * 256 + 128 - w];
            float b2 = xp[hh * 256 + 128 + w];
            float u1 = a1 + b1, v1 = a1 - b1;
            float u2 = a2 + b2, v2 = a2 - b2;
            float ue = u1 + u2, uo = u1 - u2;
            float ve = v1 - v2, vo = v1 + v2;
            if (w == 64) { ue = 0.f; uo = 0.f; ve = 0.f; vo = 0.f; }
            sue[wl * 76 + hh] = ue;
            suo[wl * 76 + hh] = uo;
            sve[wl * 76 + hh] = ve;
            svo[wl * 76 + hh] = vo;
        }
#pragma unroll
        for (int r = 0; r < 4; r++) {
            int e = t + r * 128;                // 0..511
            int ky = e & 31, wl = e >> 5;
            scs[wl * 34 + ky] = g_csA[(wc * 16 + wl + 1) * 32 + ky];
        }
        __syncthreads();
#pragma unroll 8
        for (int wl = 0; wl < 16; wl++) {
            float4 ue = *(const float4*)&sue[wl * 76 + hg * 4];
            float4 uo = *(const float4*)&suo[wl * 76 + hg * 4];
            float4 ve = *(const float4*)&sve[wl * 76 + hg * 4];
            float4 vo = *(const float4*)&svo[wl * 76 + hg * 4];
            float uev[4] = {ue.x, ue.y, ue.z, ue.w};
            float uov[4] = {uo.x, uo.y, uo.z, uo.w};
            float vev[4] = {ve.x, ve.y, ve.z, ve.w};
            float vov[4] = {vo.x, vo.y, vo.z, vo.w};
            float4 c01 = *(const float4*)&scs[wl * 34 + ky0];
            float4 c23 = *(const float4*)&scs[wl * 34 + ky0 + 2];
            float cc[4] = {c01.x, c01.z, c23.x, c23.z};
            float ss[4] = {c01.y, c01.w, c23.y, c23.w};
#pragma unroll
            for (int j = 0; j < 4; j++) {
                tr[j][0] += uev[j] * cc[0];  ti[j][0] -= vev[j] * ss[0];
                tr[j][1] += uov[j] * cc[1];  ti[j][1] -= vov[j] * ss[1];
                tr[j][2] += uev[j] * cc[2];  ti[j][2] -= vev[j] * ss[2];
                tr[j][3] += uov[j] * cc[3];  ti[j][3] -= vov[j] * ss[3];
            }
        }
        __syncthreads();
    }
    // specials: w = 0, 64, 128
#pragma unroll
    for (int j = 0; j < 4; j++) {
        int hh = hg * 4 + j;
        float x0   = xp[hh * 256];
        float x64  = xp[hh * 256 + 64];
        float x128 = xp[hh * 256 + 128];
        float x192 = xp[hh * 256 + 192];
        float u64 = x64 + x192, v64 = x64 - x192;
        tr[j][0] += x0 + u64 + x128;
        tr[j][1] += x0 - x128;
        tr[j][2] += x0 - u64 + x128;
        tr[j][3] += x0 - x128;
        ti[j][1] -= v64;
        ti[j][3] += v64;
    }
#pragma unroll
    for (int j = 0; j < 4; j++) {
        int h = hb * 64 + hg * 4 + j;
        size_t base = ((size_t)img * Hc + h) * KY + ky0;
        *(float4*)&g_T[base]     = make_float4(tr[j][0], ti[j][0], tr[j][1], ti[j][1]);
        *(float4*)&g_T[base + 2] = make_float4(tr[j][2], ti[j][2], tr[j][3], ti[j][3]);
    }
}

// ------- stage B: radix-2 H-DFT. Block = 32 h' chunk; outputs kx=2mm,2mm+1 --
__global__ void __launch_bounds__(128) kB() {
    __shared__ __align__(16) float2 Ut[32 * 34];
    __shared__ __align__(16) float2 Vt[32 * 34];
    __shared__ float2 Et[32 * 34];
    int img = blockIdx.y, hs = blockIdx.x;
    int h0 = hs * 32;
    int t = threadIdx.x;
    int ky0 = (t & 7) * 4;
    int mm0 = (t >> 3) * 2;

    float er[2][2][4], ei[2][2][4];   // [parity][m][ky]
#pragma unroll
    for (int p = 0; p < 2; p++)
#pragma unroll
        for (int m = 0; m < 2; m++)
#pragma unroll
            for (int q = 0; q < 4; q++) { er[p][m][q] = 0.f; ei[p][m][q] = 0.f; }

#pragma unroll
    for (int r = 0; r < 8; r++) {
        int e = t + r * 128; int hh = e >> 5, kk = e & 31;
        size_t ia = ((size_t)img * Hc + h0 + hh) * KY + kk;
        size_t ib = ((size_t)img * Hc + h0 + hh + 128) * KY + kk;
        float2 a = g_T[ia];
        float2 b = g_T[ib];
        Ut[hh * 34 + kk] = make_float2(a.x + b.x, a.y + b.y);
        float dx = a.x - b.x, dy = a.y - b.y;
        float2 w = g_w256[h0 + hh];   // e^{-i th}: (c,-s)
        Vt[hh * 34 + kk] = make_float2(dx * w.x + dy * w.y, dy * w.x - dx * w.y);
        Et[hh * 34 + kk] = g_E2[(h0 + hh) * 32 + kk];
    }
    __syncthreads();
#pragma unroll 4
    for (int hh = 0; hh < 32; hh++) {
        float4 u01 = *(const float4*)&Ut[hh * 34 + ky0];
        float4 u23 = *(const float4*)&Ut[hh * 34 + ky0 + 2];
        float4 v01 = *(const float4*)&Vt[hh * 34 + ky0];
        float4 v23 = *(const float4*)&Vt[hh * 34 + ky0 + 2];
        float ur[4] = {u01.x, u01.z, u23.x, u23.z};
        float ui[4] = {u01.y, u01.w, u23.y, u23.w};
        float vr[4] = {v01.x, v01.z, v23.x, v23.z};
        float vi[4] = {v01.y, v01.w, v23.y, v23.w};
#pragma unroll
        for (int m = 0; m < 2; m++) {
            float2 e = Et[hh * 34 + mm0 + m];
#pragma unroll
            for (int q = 0; q < 4; q++) {
                er[0][m][q] += e.x * ur[q] + e.y * ui[q];
                ei[0][m][q] += e.x * ui[q] - e.y * ur[q];
                er[1][m][q] += e.x * vr[q] + e.y * vi[q];
                ei[1][m][q] += e.x * vi[q] - e.y * vr[q];
            }
        }
    }
#pragma unroll
    for (int m = 0; m < 2; m++)
#pragma unroll
        for (int p = 0; p < 2; p++) {
            int kx = 2 * (mm0 + m) + p;
            size_t base = (size_t)hs * 524288 + (size_t)img * 2048 + kx * 32 + ky0;
            *(float4*)&g_XP[base] =
                make_float4(er[p][m][0], ei[p][m][0], er[p][m][1], ei[p][m][1]);
            *(float4*)&g_XP[base + 2] =
                make_float4(er[p][m][2], ei[p][m][2], er[p][m][3], ei[p][m][3]);
        }
}

// ---------------- stage C: sum partials + channel mix ----------------------
__global__ void __launch_bounds__(256) kC() {
    __shared__ float2 Ws[1024];
    __shared__ float2 Xs[256];
    int kk = blockIdx.x;
    int t  = threadIdx.x;
#pragma unroll
    for (int r = 0; r < 4; r++) Ws[t + r * 256] = g_Wt[(size_t)kk * 1024 + t + r * 256];
    float2 s = g_XP[(size_t)t * 2048 + kk];
#pragma unroll
    for (int p = 1; p < 4; p++) {
        float2 v = g_XP[(size_t)p * 524288 + (size_t)t * 2048 + kk];
        s.x += v.x; s.y += v.y;
    }
    Xs[t] = s;
    __syncthreads();
    int b = t >> 5, o = t & 31;
    float yr = 0.f, yi = 0.f;
#pragma unroll
    for (int i = 0; i < 32; i++) {
        float2 xv = Xs[b * 32 + i];
        float2 wv = Ws[i * 32 + o];
        yr += xv.x * wv.x - xv.y * wv.y;
        yi += xv.x * wv.y + xv.y * wv.x;
    }
    // write parity-split: [img][p][mm][ky]
    int p = (kk >> 5) & 1, mm = kk >> 6, ky = kk & 31;
    g_Y[(size_t)t * 2048 + p * 1024 + mm * 32 + ky] = make_float2(yr, yi);
}

// ------- stage D: radix-2 inverse H-DFT. Block = 32 h' -> 64 output rows ---
__global__ void __launch_bounds__(128) kD() {
    __shared__ __align__(16) float2 Ye[32 * 34];
    __shared__ __align__(16) float2 Yo[32 * 34];
    __shared__ float2 Eh[32 * 34];
    int img = blockIdx.y, hs = blockIdx.x;
    int h0 = hs * 32;
    int t = threadIdx.x;
    int ky0 = (t & 7) * 4;
    int hl  = (t >> 3) * 2;

#pragma unroll
    for (int r = 0; r < 8; r++) {
        int e = t + r * 128; int a = e >> 5, b = e & 31;
        Ye[a * 34 + b] = g_Y[(size_t)img * 2048 + a * 32 + b];
        Yo[a * 34 + b] = g_Y[(size_t)img * 2048 + 1024 + a * 32 + b];
        Eh[a * 34 + b] = g_E2[(h0 + a) * 32 + b];
    }
    __syncthreads();

    float aer[2][4], aei[2][4], aor[2][4], aoi[2][4];
#pragma unroll
    for (int j = 0; j < 2; j++)
#pragma unroll
        for (int q = 0; q < 4; q++) { aer[j][q]=0.f; aei[j][q]=0.f; aor[j][q]=0.f; aoi[j][q]=0.f; }

#pragma unroll 4
    for (int mm = 0; mm < 32; mm++) {
        float4 e01 = *(const float4*)&Ye[mm * 34 + ky0];
        float4 e23 = *(const float4*)&Ye[mm * 34 + ky0 + 2];
        float4 o01 = *(const float4*)&Yo[mm * 34 + ky0];
        float4 o23 = *(const float4*)&Yo[mm * 34 + ky0 + 2];
        float yer[4] = {e01.x, e01.z, e23.x, e23.z};
        float yei[4] = {e01.y, e01.w, e23.y, e23.w};
        float yor[4] = {o01.x, o01.z, o23.x, o23.z};
        float yoi[4] = {o01.y, o01.w, o23.y, o23.w};
#pragma unroll
        for (int j = 0; j < 2; j++) {
            float2 e = Eh[(hl + j) * 34 + mm];   // e^{+i}: (c, s)
#pragma unroll
            for (int q = 0; q < 4; q++) {
                aer[j][q] += e.x * yer[q] - e.y * yei[q];
                aei[j][q] += e.x * yei[q] + e.y * yer[q];
                aor[j][q] += e.x * yor[q] - e.y * yoi[q];
                aoi[j][q] += e.x * yoi[q] + e.y * yor[q];
            }
        }
    }
#pragma unroll
    for (int j = 0; j < 2; j++) {
        int hp = h0 + hl + j;
        float2 w = g_w256[hp];   // e^{+i 2pi hp/256}
        float pr[4], pi[4], mr[4], mi[4];
#pragma unroll
        for (int q = 0; q < 4; q++) {
            float sr = aor[j][q] * w.x - aoi[j][q] * w.y;
            float si = aoi[j][q] * w.x + aor[j][q] * w.y;
            pr[q] = aer[j][q] + sr; pi[q] = aei[j][q] + si;
            mr[q] = aer[j][q] - sr; mi[q] = aei[j][q] - si;
        }
        size_t b1 = ((size_t)img * Hc + hp) * KY + ky0;
        size_t b2 = ((size_t)img * Hc + hp + 128) * KY + ky0;
        *(float4*)&g_T2[b1]     = make_float4(pr[0], pi[0], pr[1], pi[1]);
        *(float4*)&g_T2[b1 + 2] = make_float4(pr[2], pi[2], pr[3], pi[3]);
        *(float4*)&g_T2[b2]     = make_float4(mr[0], mi[0], mr[1], mi[1]);
        *(float4*)&g_T2[b2 + 2] = make_float4(mr[2], mi[2], mr[3], mi[3]);
    }
}

// ------- stage E: ky-parity-folded inverse W-DFT (4 cols per cell) ---------
__global__ void __launch_bounds__(256) kE(const float* __restrict__ bias,
                                          float* __restrict__ out) {
    __shared__ __align__(16) float2 T2s[32 * 66];   // [ky][h]
    __shared__ __align__(16) float2 csE[32 * 34];   // [ky][s_local]
    int img = blockIdx.z;
    int hb  = blockIdx.y;            // 0..3 (64 h)
    int wb  = blockIdx.x;            // 0..1 (32 s)
    int t = threadIdx.x;
    int sl = (t & 15) * 2;           // 2 s per thread
    int hq = (t >> 4) * 4;           // 4 h per thread

#pragma unroll
    for (int r = 0; r < 8; r++) {
        int e = t + r * 256; int ky = e & 31, h = e >> 5;
        T2s[ky * 66 + h] = g_T2[((size_t)img * Hc + hb * 64 + h) * KY + ky];
    }
#pragma unroll
    for (int r = 0; r < 4; r++) {
        int e = t + r * 256; int ky = e >> 5, s = e & 31;
        csE[ky * 34 + s] = g_cs2E[ky * 64 + wb * 32 + s];
    }
    __syncthreads();

    float Pe[4][2], Po[4][2], Qe[4][2], Qo[4][2];
#pragma unroll
    for (int j = 0; j < 4; j++)
#pragma unroll
        for (int q = 0; q < 2; q++) { Pe[j][q]=0.f; Po[j][q]=0.f; Qe[j][q]=0.f; Qo[j][q]=0.f; }

#pragma unroll
    for (int ky = 0; ky < 32; ky++) {
        float4 t01 = *(const float4*)&T2s[ky * 66 + hq];
        float4 t23 = *(const float4*)&T2s[ky * 66 + hq + 2];
        float trv[4] = {t01.x, t01.z, t23.x, t23.z};
        float tiv[4] = {t01.y, t01.w, t23.y, t23.w};
        float4 cs = *(const float4*)&csE[ky * 34 + sl];   // c0,s0,c1,s1
        float cc[2] = {cs.x, cs.z};
        float ss[2] = {cs.y, cs.w};
        if ((ky & 1) == 0) {
#pragma unroll
            for (int j = 0; j < 4; j++)
#pragma unroll
                for (int q = 0; q < 2; q++) {
                    Pe[j][q] += cc[q] * trv[j];
                    Qe[j][q] += ss[q] * tiv[j];
                }
        } else {
#pragma unroll
            for (int j = 0; j < 4; j++)
#pragma unroll
                for (int q = 0; q < 2; q++) {
                    Po[j][q] += cc[q] * trv[j];
                    Qo[j][q] += ss[q] * tiv[j];
                }
        }
    }

    float bv = bias[img & 31];
#pragma unroll
    for (int j = 0; j < 4; j++) {
        size_t row = ((size_t)img * Hc + hb * 64 + hq + j) * Wc;
#pragma unroll
        for (int q = 0; q < 2; q++) {
            int tw = wb * 32 + sl + q + 1;      // 1..64
            float Pp = Pe[j][q] + Po[j][q], Pm = Pe[j][q] - Po[j][q];
            float Qp = Qe[j][q] + Qo[j][q], Qm = Qe[j][q] - Qo[j][q];
            out[row + tw]        = Pp - Qp + bv;
            out[row + 256 - tw]  = Pp + Qp + bv;
            out[row + 128 - tw]  = Pm + Qm + bv;
            out[row + 128 + tw]  = Pm - Qm + bv;
        }
    }
}

// ---------------- stage E0: w = 0 and w = 128 columns ----------------------
__global__ void kE0(const float* __restrict__ bias, float* __restrict__ out) {
    int img = blockIdx.x;
    int t = threadIdx.x, l = t & 31, wp = t >> 5;
    float coef = ((l == 0) ? 1.f : 2.f) * (1.f / 65536.f);
    float sgn  = (l & 1) ? -1.f : 1.f;
    float bv = bias[img & 31];
    for (int it = 0; it < 32; it++) {
        int h = wp + it * 8;
        float a = coef * g_T2[((size_t)img * Hc + h) * KY + l].x;
        float b = sgn * a;
#pragma unroll
        for (int s = 16; s; s >>= 1) {
            a += __shfl_xor_sync(0xffffffffu, a, s);
            b += __shfl_xor_sync(0xffffffffu, b, s);
        }
        if (l == 0) {
            size_t row = ((size_t)img * Hc + h) * Wc;
            out[row]       = a + bv;
            out[row + 128] = b + bv;
        }
    }
}

// ---------------- launch ----------------
extern "C" void kernel_launch(void* const* d_in, const int* in_sizes, int n_in,
                              void* d_out, int out_size) {
    const float* x    = (const float*)d_in[0];
    const float* w1r  = (const float*)d_in[1];
    const float* w1i  = (const float*)d_in[2];
    const float* w2r  = (const float*)d_in[3];
    const float* w2i  = (const float*)d_in[4];
    const float* bias = (const float*)d_in[5];
    float* out = (float*)d_out;

    k_tables<<<48, 256>>>();
    k_wtrans<<<dim3(32, 32, 2), dim3(32, 8)>>>(w1r, w1i, w2r, w2i);
    kA<<<dim3(4, 256), 128>>>(x);
    kB<<<dim3(4, 256), 128>>>();
    kC<<<2048, 256>>>();
    kD<<<dim3(4, 256), 128>>>();
    kE<<<dim3(2, 4, 256), 256>>>(bias, out);
    kE0<<<256, 256>>>(bias, out);
}